// round 7
// baseline (speedup 1.0000x reference)
#include <cuda_runtime.h>
#include <cuda_fp16.h>
#include <cstdint>

#define M_TOT 8192
#define K_TOT 3584
#define N_ALL 4608
#define NQ    3584
#define NKV   512
#define SEQ   4096

#define QSZ ((size_t)2*28*4096*128)
#define KSZ ((size_t)2*4*4096*128)

#define BM 256
#define BN 128
#define BK 32
#define LDA 40     // halfs per A smem row (32 + 8 pad)
#define LDB 136    // halfs per B smem row (128 + 8 pad)
#define NKITER (K_TOT / BK)   // 112
#define STAGES 4
#define A_STG (BM * LDA)      // 10240 halfs = 20480 B
#define B_STG (BK * LDB)      // 4352 halfs = 8704 B
#define STG_HALFS (A_STG + B_STG)
#define DYN_SMEM (STAGES * STG_HALFS * 2)   // 116736 B

// Static device scratch (no allocation allowed in kernel_launch)
__device__ __align__(16) __half g_A[(size_t)M_TOT * K_TOT];   // hidden fp16
__device__ __align__(16) __half g_W[(size_t)K_TOT * N_ALL];   // [Wq|Wk|Wv] fp16, row-major [K][N_ALL]
__device__ __align__(16) float  g_bias[N_ALL];

// ---------------- conversion kernels ----------------

__global__ void conv_hidden(const float* __restrict__ src) {
    size_t i = ((size_t)blockIdx.x * 256 + threadIdx.x) * 8;
    float4 f0 = *(const float4*)(src + i);
    float4 f1 = *(const float4*)(src + i + 4);
    __half2 h0 = __floats2half2_rn(f0.x, f0.y);
    __half2 h1 = __floats2half2_rn(f0.z, f0.w);
    __half2 h2 = __floats2half2_rn(f1.x, f1.y);
    __half2 h3 = __floats2half2_rn(f1.z, f1.w);
    uint4 u;
    u.x = *(uint32_t*)&h0; u.y = *(uint32_t*)&h1;
    u.z = *(uint32_t*)&h2; u.w = *(uint32_t*)&h3;
    *(uint4*)(&g_A[i]) = u;
}

__global__ void conv_w(const float* __restrict__ Wq,
                       const float* __restrict__ Wk,
                       const float* __restrict__ Wv) {
    size_t idx = (size_t)blockIdx.x * 256 + threadIdx.x;   // one idx = 4 elements
    size_t n4 = idx % (N_ALL / 4);
    size_t k  = idx / (N_ALL / 4);
    int n = (int)(n4 * 4);
    const float* s;
    if (n < NQ)            s = Wq + k * NQ  + n;
    else if (n < NQ + NKV) s = Wk + k * NKV + (n - NQ);
    else                   s = Wv + k * NKV + (n - NQ - NKV);
    float4 f = *(const float4*)s;
    __half2 h0 = __floats2half2_rn(f.x, f.y);
    __half2 h1 = __floats2half2_rn(f.z, f.w);
    uint2 u;
    u.x = *(uint32_t*)&h0; u.y = *(uint32_t*)&h1;
    *(uint2*)(&g_W[k * N_ALL + n]) = u;
}

__global__ void conv_bias(const float* __restrict__ bq,
                          const float* __restrict__ bk,
                          const float* __restrict__ bv) {
    int n = blockIdx.x * 256 + threadIdx.x;
    if (n >= N_ALL) return;
    float v;
    if (n < NQ)            v = bq[n];
    else if (n < NQ + NKV) v = bk[n - NQ];
    else                   v = bv[n - NQ - NKV];
    g_bias[n] = v;
}

// ---------------- main fused GEMM + RoPE kernel ----------------

#define CP16(dst_u32, src_ptr) \
    asm volatile("cp.async.cg.shared.global [%0], [%1], 16;\n" :: "r"(dst_u32), "l"(src_ptr))

#define MMA16816(c, a, b0_, b1_) \
    asm volatile("mma.sync.aligned.m16n8k16.row.col.f32.f16.f16.f32 " \
        "{%0,%1,%2,%3}, {%4,%5,%6,%7}, {%8,%9}, {%0,%1,%2,%3};\n" \
        : "+f"(c[0]), "+f"(c[1]), "+f"(c[2]), "+f"(c[3]) \
        : "r"(a[0]), "r"(a[1]), "r"(a[2]), "r"(a[3]), "r"(b0_), "r"(b1_))

__global__ __launch_bounds__(256, 1)
void qkv_gemm_rope(const float* __restrict__ cosb,
                   const float* __restrict__ sinb,
                   float* __restrict__ out) {
    extern __shared__ __half sm[];

    const int tid  = threadIdx.x;
    const int lane = tid & 31;
    const int wid  = tid >> 5;
    const int wm   = wid >> 1;    // 0..3 -> 64 rows each
    const int wn   = wid & 1;     // 0..1 -> n-tiles {wn*32..+31} and {64+wn*32..+31}

    const int ht = blockIdx.x;    // 0..35 head tile (fastest -> wave shares W in L2)
    const int mt = blockIdx.y;    // 0..31
    const int m0 = mt * BM;
    const int n0g = ht * BN;

    const __half* Ag = g_A + (size_t)m0 * K_TOT;
    const __half* Bg = g_W + n0g;

    const uint32_t smA = (uint32_t)__cvta_generic_to_shared(sm);

    // warp tile: 64 m x 64 n (as 2x 32-wide col chunks paired for RoPE)
    float acc[4][8][4];
    #pragma unroll
    for (int i = 0; i < 4; i++)
        #pragma unroll
        for (int j = 0; j < 8; j++)
            #pragma unroll
            for (int c = 0; c < 4; c++)
                acc[i][j][c] = 0.0f;

    auto loadStage = [&](int buf, int kt) {
        const int k0 = kt * BK;
        const uint32_t aBase = smA + (uint32_t)(buf * STG_HALFS) * 2;
        const uint32_t bBase = aBase + A_STG * 2;
        #pragma unroll
        for (int l = 0; l < 4; l++) {
            int idx = tid + l * 256;           // A: 1024 chunks of 16B
            int r = idx >> 2, ch = (idx & 3) << 3;
            CP16(aBase + (uint32_t)(r * LDA + ch) * 2,
                 Ag + (size_t)r * K_TOT + k0 + ch);
        }
        #pragma unroll
        for (int l = 0; l < 2; l++) {
            int idx = tid + l * 256;           // B: 512 chunks of 16B
            int r = idx >> 4, ch = (idx & 15) << 3;
            CP16(bBase + (uint32_t)(r * LDB + ch) * 2,
                 Bg + (size_t)(k0 + r) * N_ALL + ch);
        }
        asm volatile("cp.async.commit_group;\n");
    };

    auto computeStage = [&](int buf) {
        const uint32_t aBase = smA + (uint32_t)(buf * STG_HALFS) * 2;
        const uint32_t bBase = aBase + A_STG * 2;
        #pragma unroll
        for (int ks = 0; ks < 2; ks++) {
            const int kk = ks * 16;
            uint32_t a[4][4];
            #pragma unroll
            for (int i = 0; i < 4; i++) {
                uint32_t addr = aBase +
                    (uint32_t)(((wm * 64 + i * 16 + (lane & 15)) * LDA) + kk + ((lane >> 4) << 3)) * 2;
                asm volatile("ldmatrix.sync.aligned.m8n8.x4.shared.b16 {%0,%1,%2,%3}, [%4];\n"
                    : "=r"(a[i][0]), "=r"(a[i][1]), "=r"(a[i][2]), "=r"(a[i][3])
                    : "r"(addr));
            }
            #pragma unroll
            for (int g = 0; g < 4; g++) {
                const int nb = (g < 2) ? (wn * 32 + g * 16) : (64 + wn * 32 + (g - 2) * 16);
                uint32_t addr = bBase +
                    (uint32_t)(((kk + (lane & 15)) * LDB) + nb + ((lane >> 4) << 3)) * 2;
                uint32_t b0, b1, b2, b3;
                asm volatile("ldmatrix.sync.aligned.m8n8.x4.trans.shared.b16 {%0,%1,%2,%3}, [%4];\n"
                    : "=r"(b0), "=r"(b1), "=r"(b2), "=r"(b3)
                    : "r"(addr));
                #pragma unroll
                for (int i = 0; i < 4; i++) {
                    MMA16816(acc[i][2 * g],     a[i], b0, b1);
                    MMA16816(acc[i][2 * g + 1], a[i], b2, b3);
                }
            }
        }
    };

    // prologue: issue STAGES-1 loads
    #pragma unroll
    for (int s = 0; s < STAGES - 1; s++) loadStage(s, s);

    #pragma unroll 4
    for (int kt = 0; kt < NKITER; kt++) {
        const int buf = kt & (STAGES - 1);
        asm volatile("cp.async.wait_group %0;\n" :: "n"(STAGES - 2));
        __syncthreads();
        const int nxt = kt + STAGES - 1;
        if (nxt < NKITER) loadStage(nxt & (STAGES - 1), nxt);
        else              asm volatile("cp.async.commit_group;\n");   // keep group count uniform
        computeStage(buf);
    }

    // ---------------- epilogue: bias + RoPE + permuted store ----------------
    const bool isQ = (ht < 28);
    const bool isK = (ht >= 28) && (ht < 32);
    const bool doRope = (ht < 32);
    const float* bias = g_bias + ht * 128;

    #pragma unroll
    for (int i = 0; i < 4; i++) {
        #pragma unroll
        for (int rr = 0; rr < 2; rr++) {
            const int r = wm * 64 + i * 16 + (lane >> 2) + rr * 8;
            const int m = m0 + r;
            const int bb = m >> 12;      // batch
            const int s  = m & 4095;     // seq pos
            size_t rowBase;
            if (isQ)      rowBase = ((size_t)(bb * 28 + ht) * SEQ + s) * 128;
            else if (isK) rowBase = QSZ + ((size_t)(bb * 4 + (ht - 28)) * SEQ + s) * 128;
            else          rowBase = QSZ + KSZ + ((size_t)(bb * 4 + (ht - 32)) * SEQ + s) * 128;
            const float* cs = cosb + (size_t)m * 128;
            const float* sn = sinb + (size_t)m * 128;
            #pragma unroll
            for (int jn = 0; jn < 4; jn++) {
                const int dlo = wn * 32 + jn * 8 + ((lane & 3) << 1);
                const int dhi = dlo + 64;
                float2 bl = *(const float2*)(bias + dlo);
                float2 bh = *(const float2*)(bias + dhi);
                float vl0 = acc[i][jn][rr * 2 + 0] + bl.x;
                float vl1 = acc[i][jn][rr * 2 + 1] + bl.y;
                float vh0 = acc[i][jn + 4][rr * 2 + 0] + bh.x;
                float vh1 = acc[i][jn + 4][rr * 2 + 1] + bh.y;
                float2 olo, ohi;
                if (doRope) {
                    float2 cl = *(const float2*)(cs + dlo);
                    float2 sl = *(const float2*)(sn + dlo);
                    float2 ch = *(const float2*)(cs + dhi);
                    float2 sh = *(const float2*)(sn + dhi);
                    olo.x = vl0 * cl.x - vh0 * sl.x;    // d < 64: q*cos - q[d+64]*sin
                    olo.y = vl1 * cl.y - vh1 * sl.y;
                    ohi.x = vh0 * ch.x + vl0 * sh.x;    // d >= 64: q*cos + q[d-64]*sin
                    ohi.y = vh1 * ch.y + vl1 * sh.y;
                } else {
                    olo = make_float2(vl0, vl1);
                    ohi = make_float2(vh0, vh1);
                }
                *(float2*)(out + rowBase + dlo) = olo;
                *(float2*)(out + rowBase + dhi) = ohi;
            }
        }
    }
}

// ---------------- launch ----------------

extern "C" void kernel_launch(void* const* d_in, const int* in_sizes, int n_in,
                              void* d_out, int out_size) {
    const float* hs   = (const float*)d_in[0];
    const float* cosb = (const float*)d_in[1];
    const float* sinb = (const float*)d_in[2];
    const float* Wq   = (const float*)d_in[3];
    const float* bq   = (const float*)d_in[4];
    const float* Wk   = (const float*)d_in[5];
    const float* bk   = (const float*)d_in[6];
    const float* Wv   = (const float*)d_in[7];
    const float* bv   = (const float*)d_in[8];
    float* out = (float*)d_out;

    // fp32 -> fp16 conversion passes (every call; no caching)
    conv_hidden<<<14336, 256>>>(hs);                 // 29360128 / 8 / 256
    conv_w<<<16128, 256>>>(Wq, Wk, Wv);              // 16515072 / 4 / 256
    conv_bias<<<18, 256>>>(bq, bk, bv);

    cudaFuncSetAttribute(qkv_gemm_rope, cudaFuncAttributeMaxDynamicSharedMemorySize, DYN_SMEM);
    dim3 grid(N_ALL / BN, M_TOT / BM);               // 36 x 32 (ht fastest)
    qkv_gemm_rope<<<grid, 256, DYN_SMEM>>>(cosb, sinb, out);
}

// round 10
// speedup vs baseline: 1.1201x; 1.1201x over previous
#include <cuda_runtime.h>
#include <cuda_fp16.h>
#include <cstdint>

#define M_TOT 8192
#define K_TOT 3584
#define N_ALL 4608
#define NQ    3584
#define NKV   512
#define SEQ   4096

#define QSZ ((size_t)2*28*4096*128)
#define KSZ ((size_t)2*4*4096*128)

#define BM 128
#define BN 128
#define BK 32
#define LDA 40     // halfs per A smem row (32 + 8 pad)
#define LDB 136    // halfs per B smem row (128 + 8 pad)
#define NKITER (K_TOT / BK)   // 112
#define STAGES 4
#define A_STG (BM * LDA)      // 5120 halfs
#define B_STG (BK * LDB)      // 4352 halfs
#define STG_HALFS (A_STG + B_STG)
#define DYN_SMEM (STAGES * STG_HALFS * 2)   // 75776 B

// Static device scratch (no allocation allowed in kernel_launch)
__device__ __align__(16) __half g_A[(size_t)M_TOT * K_TOT];   // hidden fp16
__device__ __align__(16) __half g_W[(size_t)K_TOT * N_ALL];   // [Wq|Wk|Wv] fp16, row-major [K][N_ALL]
__device__ __align__(16) float  g_bias[N_ALL];

// ---------------- conversion kernels ----------------

__global__ void conv_hidden(const float* __restrict__ src) {
    size_t i = ((size_t)blockIdx.x * 256 + threadIdx.x) * 8;
    float4 f0 = *(const float4*)(src + i);
    float4 f1 = *(const float4*)(src + i + 4);
    __half2 h0 = __floats2half2_rn(f0.x, f0.y);
    __half2 h1 = __floats2half2_rn(f0.z, f0.w);
    __half2 h2 = __floats2half2_rn(f1.x, f1.y);
    __half2 h3 = __floats2half2_rn(f1.z, f1.w);
    uint4 u;
    u.x = *(uint32_t*)&h0; u.y = *(uint32_t*)&h1;
    u.z = *(uint32_t*)&h2; u.w = *(uint32_t*)&h3;
    *(uint4*)(&g_A[i]) = u;
}

__global__ void conv_w(const float* __restrict__ Wq,
                       const float* __restrict__ Wk,
                       const float* __restrict__ Wv) {
    size_t idx = (size_t)blockIdx.x * 256 + threadIdx.x;   // one idx = 4 elements
    size_t n4 = idx % (N_ALL / 4);
    size_t k  = idx / (N_ALL / 4);
    int n = (int)(n4 * 4);
    const float* s;
    if (n < NQ)            s = Wq + k * NQ  + n;
    else if (n < NQ + NKV) s = Wk + k * NKV + (n - NQ);
    else                   s = Wv + k * NKV + (n - NQ - NKV);
    float4 f = *(const float4*)s;
    __half2 h0 = __floats2half2_rn(f.x, f.y);
    __half2 h1 = __floats2half2_rn(f.z, f.w);
    uint2 u;
    u.x = *(uint32_t*)&h0; u.y = *(uint32_t*)&h1;
    *(uint2*)(&g_W[k * N_ALL + n]) = u;
}

__global__ void conv_bias(const float* __restrict__ bq,
                          const float* __restrict__ bk,
                          const float* __restrict__ bv) {
    int n = blockIdx.x * 256 + threadIdx.x;
    if (n >= N_ALL) return;
    float v;
    if (n < NQ)            v = bq[n];
    else if (n < NQ + NKV) v = bk[n - NQ];
    else                   v = bv[n - NQ - NKV];
    g_bias[n] = v;
}

// ---------------- main fused GEMM + RoPE kernel ----------------

#define CP16(dst_u32, src_ptr) \
    asm volatile("cp.async.cg.shared.global [%0], [%1], 16;\n" :: "r"(dst_u32), "l"(src_ptr))

#define MMA16816(c, a, b0_, b1_) \
    asm volatile("mma.sync.aligned.m16n8k16.row.col.f32.f16.f16.f32 " \
        "{%0,%1,%2,%3}, {%4,%5,%6,%7}, {%8,%9}, {%0,%1,%2,%3};\n" \
        : "+f"(c[0]), "+f"(c[1]), "+f"(c[2]), "+f"(c[3]) \
        : "r"(a[0]), "r"(a[1]), "r"(a[2]), "r"(a[3]), "r"(b0_), "r"(b1_))

__global__ __launch_bounds__(256, 2)
void qkv_gemm_rope(const float* __restrict__ cosb,
                   const float* __restrict__ sinb,
                   float* __restrict__ out) {
    extern __shared__ __half sm[];

    const int tid  = threadIdx.x;
    const int lane = tid & 31;
    const int wid  = tid >> 5;
    const int wm   = wid >> 1;    // 0..3 -> 32 rows each
    const int wn   = wid & 1;     // 0..1 -> n-tiles {wn*32..+31} and {64+wn*32..+31}

    const int ht = blockIdx.x;    // 0..35 head tile (fastest -> wave shares W in L2)
    const int mt = blockIdx.y;    // 0..63
    const int m0 = mt * BM;
    const int n0g = ht * BN;

    const __half* Ag = g_A + (size_t)m0 * K_TOT;
    const __half* Bg = g_W + n0g;

    const uint32_t smA = (uint32_t)__cvta_generic_to_shared(sm);

    float acc[2][8][4];
    #pragma unroll
    for (int i = 0; i < 2; i++)
        #pragma unroll
        for (int j = 0; j < 8; j++)
            #pragma unroll
            for (int c = 0; c < 4; c++)
                acc[i][j][c] = 0.0f;

    auto loadStage = [&](int buf, int kt) {
        const int k0 = kt * BK;
        const uint32_t aBase = smA + (uint32_t)(buf * STG_HALFS) * 2;
        const uint32_t bBase = aBase + A_STG * 2;
        #pragma unroll
        for (int l = 0; l < 2; l++) {
            int idx = tid + l * 256;           // A: 512 chunks of 16B
            int r = idx >> 2, ch = (idx & 3) << 3;
            CP16(aBase + (uint32_t)(r * LDA + ch) * 2,
                 Ag + (size_t)r * K_TOT + k0 + ch);
        }
        #pragma unroll
        for (int l = 0; l < 2; l++) {
            int idx = tid + l * 256;           // B: 512 chunks of 16B
            int r = idx >> 4, ch = (idx & 15) << 3;
            CP16(bBase + (uint32_t)(r * LDB + ch) * 2,
                 Bg + (size_t)(k0 + r) * N_ALL + ch);
        }
        asm volatile("cp.async.commit_group;\n");
    };

    auto computeStage = [&](int buf) {
        const uint32_t aBase = smA + (uint32_t)(buf * STG_HALFS) * 2;
        const uint32_t bBase = aBase + A_STG * 2;
        #pragma unroll
        for (int ks = 0; ks < 2; ks++) {
            const int kk = ks * 16;
            uint32_t a[2][4];
            uint32_t b[4][4];
            // ---- batch ALL fragment loads first (latency overlap) ----
            #pragma unroll
            for (int i = 0; i < 2; i++) {
                uint32_t addr = aBase +
                    (uint32_t)(((wm * 32 + i * 16 + (lane & 15)) * LDA) + kk + ((lane >> 4) << 3)) * 2;
                asm volatile("ldmatrix.sync.aligned.m8n8.x4.shared.b16 {%0,%1,%2,%3}, [%4];\n"
                    : "=r"(a[i][0]), "=r"(a[i][1]), "=r"(a[i][2]), "=r"(a[i][3])
                    : "r"(addr));
            }
            #pragma unroll
            for (int g = 0; g < 4; g++) {
                const int nb = (g < 2) ? (wn * 32 + g * 16) : (64 + wn * 32 + (g - 2) * 16);
                uint32_t addr = bBase +
                    (uint32_t)(((kk + (lane & 15)) * LDB) + nb + ((lane >> 4) << 3)) * 2;
                asm volatile("ldmatrix.sync.aligned.m8n8.x4.trans.shared.b16 {%0,%1,%2,%3}, [%4];\n"
                    : "=r"(b[g][0]), "=r"(b[g][1]), "=r"(b[g][2]), "=r"(b[g][3])
                    : "r"(addr));
            }
            // ---- then ALL MMAs ----
            #pragma unroll
            for (int g = 0; g < 4; g++) {
                #pragma unroll
                for (int i = 0; i < 2; i++) {
                    MMA16816(acc[i][2 * g],     a[i], b[g][0], b[g][1]);
                    MMA16816(acc[i][2 * g + 1], a[i], b[g][2], b[g][3]);
                }
            }
        }
    };

    // prologue: issue STAGES-1 loads
    #pragma unroll
    for (int s = 0; s < STAGES - 1; s++) loadStage(s, s);

    #pragma unroll 4
    for (int kt = 0; kt < NKITER; kt++) {
        const int buf = kt & (STAGES - 1);
        asm volatile("cp.async.wait_group %0;\n" :: "n"(STAGES - 2));
        __syncthreads();
        const int nxt = kt + STAGES - 1;
        if (nxt < NKITER) loadStage(nxt & (STAGES - 1), nxt);
        else              asm volatile("cp.async.commit_group;\n");   // keep group count uniform
        computeStage(buf);
    }

    // ---------------- epilogue: bias + RoPE + permuted store ----------------
    const bool isQ = (ht < 28);
    const bool isK = (ht >= 28) && (ht < 32);
    const bool doRope = (ht < 32);
    const float* bias = g_bias + ht * 128;

    #pragma unroll
    for (int i = 0; i < 2; i++) {
        #pragma unroll
        for (int rr = 0; rr < 2; rr++) {
            const int r = wm * 32 + i * 16 + (lane >> 2) + rr * 8;
            const int m = m0 + r;
            const int bb = m >> 12;      // batch
            const int s  = m & 4095;     // seq pos
            size_t rowBase;
            if (isQ)      rowBase = ((size_t)(bb * 28 + ht) * SEQ + s) * 128;
            else if (isK) rowBase = QSZ + ((size_t)(bb * 4 + (ht - 28)) * SEQ + s) * 128;
            else          rowBase = QSZ + KSZ + ((size_t)(bb * 4 + (ht - 32)) * SEQ + s) * 128;
            const float* cs = cosb + (size_t)m * 128;
            const float* sn = sinb + (size_t)m * 128;
            #pragma unroll
            for (int jn = 0; jn < 4; jn++) {
                const int dlo = wn * 32 + jn * 8 + ((lane & 3) << 1);
                const int dhi = dlo + 64;
                float2 bl = *(const float2*)(bias + dlo);
                float2 bh = *(const float2*)(bias + dhi);
                float vl0 = acc[i][jn][rr * 2 + 0] + bl.x;
                float vl1 = acc[i][jn][rr * 2 + 1] + bl.y;
                float vh0 = acc[i][jn + 4][rr * 2 + 0] + bh.x;
                float vh1 = acc[i][jn + 4][rr * 2 + 1] + bh.y;
                float2 olo, ohi;
                if (doRope) {
                    float2 cl = *(const float2*)(cs + dlo);
                    float2 sl = *(const float2*)(sn + dlo);
                    float2 ch = *(const float2*)(cs + dhi);
                    float2 sh = *(const float2*)(sn + dhi);
                    olo.x = vl0 * cl.x - vh0 * sl.x;    // d < 64: q*cos - q[d+64]*sin
                    olo.y = vl1 * cl.y - vh1 * sl.y;
                    ohi.x = vh0 * ch.x + vl0 * sh.x;    // d >= 64: q*cos + q[d-64]*sin
                    ohi.y = vh1 * ch.y + vl1 * sh.y;
                } else {
                    olo = make_float2(vl0, vl1);
                    ohi = make_float2(vh0, vh1);
                }
                *(float2*)(out + rowBase + dlo) = olo;
                *(float2*)(out + rowBase + dhi) = ohi;
            }
        }
    }
}

// ---------------- launch ----------------

extern "C" void kernel_launch(void* const* d_in, const int* in_sizes, int n_in,
                              void* d_out, int out_size) {
    const float* hs   = (const float*)d_in[0];
    const float* cosb = (const float*)d_in[1];
    const float* sinb = (const float*)d_in[2];
    const float* Wq   = (const float*)d_in[3];
    const float* bq   = (const float*)d_in[4];
    const float* Wk   = (const float*)d_in[5];
    const float* bk   = (const float*)d_in[6];
    const float* Wv   = (const float*)d_in[7];
    const float* bv   = (const float*)d_in[8];
    float* out = (float*)d_out;

    // fp32 -> fp16 conversion passes (every call; no caching)
    conv_hidden<<<14336, 256>>>(hs);                 // 29360128 / 8 / 256
    conv_w<<<16128, 256>>>(Wq, Wk, Wv);              // 16515072 / 4 / 256
    conv_bias<<<18, 256>>>(bq, bk, bv);

    cudaFuncSetAttribute(qkv_gemm_rope, cudaFuncAttributeMaxDynamicSharedMemorySize, DYN_SMEM);
    dim3 grid(N_ALL / BN, M_TOT / BM);               // 36 x 64 (ht fastest)
    qkv_gemm_rope<<<grid, 256, DYN_SMEM>>>(cosb, sinb, out);
}

// round 13
// speedup vs baseline: 1.2685x; 1.1324x over previous
#include <cuda_runtime.h>
#include <cuda_fp16.h>
#include <cstdint>

#define M_TOT 8192
#define K_TOT 3584
#define N_ALL 4608
#define NQ    3584
#define NKV   512
#define SEQ   4096

#define QSZ ((size_t)2*28*4096*128)
#define KSZ ((size_t)2*4*4096*128)

#define BM 128
#define BN 256
#define BK 32
#define LDA 40      // halfs per A smem row (32 + 8 pad)
#define LDB 264     // halfs per B smem row (256 + 8 pad)
#define NKITER (K_TOT / BK)   // 112
#define STAGES 4
#define A_STG (BM * LDA)      // 5120 halfs
#define B_STG (BK * LDB)      // 8448 halfs
#define STG_HALFS (A_STG + B_STG)          // 13568
#define DYN_SMEM (STAGES * STG_HALFS * 2)  // 108544 B

#define NTHREADS 512

// Static device scratch (no allocation allowed in kernel_launch)
__device__ __align__(16) __half g_A[(size_t)M_TOT * K_TOT];   // hidden fp16
__device__ __align__(16) __half g_W[(size_t)K_TOT * N_ALL];   // [Wq|Wk|Wv] fp16, row-major [K][N_ALL]
__device__ __align__(16) float  g_bias[N_ALL];

// ---------------- conversion kernels ----------------

__global__ void conv_hidden(const float* __restrict__ src) {
    size_t i = ((size_t)blockIdx.x * 256 + threadIdx.x) * 8;
    float4 f0 = *(const float4*)(src + i);
    float4 f1 = *(const float4*)(src + i + 4);
    __half2 h0 = __floats2half2_rn(f0.x, f0.y);
    __half2 h1 = __floats2half2_rn(f0.z, f0.w);
    __half2 h2 = __floats2half2_rn(f1.x, f1.y);
    __half2 h3 = __floats2half2_rn(f1.z, f1.w);
    uint4 u;
    u.x = *(uint32_t*)&h0; u.y = *(uint32_t*)&h1;
    u.z = *(uint32_t*)&h2; u.w = *(uint32_t*)&h3;
    *(uint4*)(&g_A[i]) = u;
}

__global__ void conv_w(const float* __restrict__ Wq,
                       const float* __restrict__ Wk,
                       const float* __restrict__ Wv) {
    size_t idx = (size_t)blockIdx.x * 256 + threadIdx.x;   // one idx = 4 elements
    size_t n4 = idx % (N_ALL / 4);
    size_t k  = idx / (N_ALL / 4);
    int n = (int)(n4 * 4);
    const float* s;
    if (n < NQ)            s = Wq + k * NQ  + n;
    else if (n < NQ + NKV) s = Wk + k * NKV + (n - NQ);
    else                   s = Wv + k * NKV + (n - NQ - NKV);
    float4 f = *(const float4*)s;
    __half2 h0 = __floats2half2_rn(f.x, f.y);
    __half2 h1 = __floats2half2_rn(f.z, f.w);
    uint2 u;
    u.x = *(uint32_t*)&h0; u.y = *(uint32_t*)&h1;
    *(uint2*)(&g_W[k * N_ALL + n]) = u;
}

__global__ void conv_bias(const float* __restrict__ bq,
                          const float* __restrict__ bk,
                          const float* __restrict__ bv) {
    int n = blockIdx.x * 256 + threadIdx.x;
    if (n >= N_ALL) return;
    float v;
    if (n < NQ)            v = bq[n];
    else if (n < NQ + NKV) v = bk[n - NQ];
    else                   v = bv[n - NQ - NKV];
    g_bias[n] = v;
}

// ---------------- main fused GEMM + RoPE kernel ----------------

#define CP16(dst_u32, src_ptr) \
    asm volatile("cp.async.cg.shared.global [%0], [%1], 16;\n" :: "r"(dst_u32), "l"(src_ptr))

#define MMA16816(c, a, b0_, b1_) \
    asm volatile("mma.sync.aligned.m16n8k16.row.col.f32.f16.f16.f32 " \
        "{%0,%1,%2,%3}, {%4,%5,%6,%7}, {%8,%9}, {%0,%1,%2,%3};\n" \
        : "+f"(c[0]), "+f"(c[1]), "+f"(c[2]), "+f"(c[3]) \
        : "r"(a[0]), "r"(a[1]), "r"(a[2]), "r"(a[3]), "r"(b0_), "r"(b1_))

__global__ __launch_bounds__(NTHREADS, 1)
void qkv_gemm_rope(const float* __restrict__ cosb,
                   const float* __restrict__ sinb,
                   float* __restrict__ out) {
    extern __shared__ __half sm[];

    const int tid  = threadIdx.x;
    const int lane = tid & 31;
    const int wid  = tid >> 5;      // 0..15
    const int wm   = wid >> 2;      // 0..3 -> 32 rows each
    const int wn   = wid & 3;       // 0..3 -> head hd=wn>>1, half=wn&1

    const int ht = blockIdx.x;      // 0..17 (2 heads per tile; never straddles Q/K/V)
    const int mt = blockIdx.y;      // 0..63
    const int m0 = mt * BM;
    const int n0g = ht * BN;

    const int hd   = wn >> 1;       // which head of the pair
    const int half = wn & 1;        // which 32-col half of each RoPE block

    const __half* Ag = g_A + (size_t)m0 * K_TOT;
    const __half* Bg = g_W + n0g;

    const uint32_t smA = (uint32_t)__cvta_generic_to_shared(sm);

    float acc[2][8][4];
    #pragma unroll
    for (int i = 0; i < 2; i++)
        #pragma unroll
        for (int j = 0; j < 8; j++)
            #pragma unroll
            for (int c = 0; c < 4; c++)
                acc[i][j][c] = 0.0f;

    auto loadStage = [&](int buf, int kt) {
        const int k0 = kt * BK;
        const uint32_t aBase = smA + (uint32_t)(buf * STG_HALFS) * 2;
        const uint32_t bBase = aBase + A_STG * 2;
        {   // A: 512 chunks of 16B, 1 per thread
            int r = tid >> 2, ch = (tid & 3) << 3;
            CP16(aBase + (uint32_t)(r * LDA + ch) * 2,
                 Ag + (size_t)r * K_TOT + k0 + ch);
        }
        #pragma unroll
        for (int l = 0; l < 2; l++) {   // B: 1024 chunks of 16B
            int idx = tid + l * NTHREADS;
            int r = idx >> 5, ch = (idx & 31) << 3;
            CP16(bBase + (uint32_t)(r * LDB + ch) * 2,
                 Bg + (size_t)(k0 + r) * N_ALL + ch);
        }
        asm volatile("cp.async.commit_group;\n");
    };

    auto computeKs = [&](int buf, int ks) {
        const uint32_t aBase = smA + (uint32_t)(buf * STG_HALFS) * 2;
        const uint32_t bBase = aBase + A_STG * 2;
        const int kk = ks * 16;
        uint32_t a[2][4];
        uint32_t b[4][4];
        #pragma unroll
        for (int i = 0; i < 2; i++) {
            uint32_t addr = aBase +
                (uint32_t)(((wm * 32 + i * 16 + (lane & 15)) * LDA) + kk + ((lane >> 4) << 3)) * 2;
            asm volatile("ldmatrix.sync.aligned.m8n8.x4.shared.b16 {%0,%1,%2,%3}, [%4];\n"
                : "=r"(a[i][0]), "=r"(a[i][1]), "=r"(a[i][2]), "=r"(a[i][3])
                : "r"(addr));
        }
        #pragma unroll
        for (int g = 0; g < 4; g++) {
            const int nb = hd * 128 + ((g < 2) ? (half * 32 + g * 16)
                                               : (64 + half * 32 + (g - 2) * 16));
            uint32_t addr = bBase +
                (uint32_t)(((kk + (lane & 15)) * LDB) + nb + ((lane >> 4) << 3)) * 2;
            asm volatile("ldmatrix.sync.aligned.m8n8.x4.trans.shared.b16 {%0,%1,%2,%3}, [%4];\n"
                : "=r"(b[g][0]), "=r"(b[g][1]), "=r"(b[g][2]), "=r"(b[g][3])
                : "r"(addr));
        }
        #pragma unroll
        for (int g = 0; g < 4; g++) {
            #pragma unroll
            for (int i = 0; i < 2; i++) {
                MMA16816(acc[i][2 * g],     a[i], b[g][0], b[g][1]);
                MMA16816(acc[i][2 * g + 1], a[i], b[g][2], b[g][3]);
            }
        }
    };

    // prologue: issue STAGES-1 loads
    #pragma unroll
    for (int s = 0; s < STAGES - 1; s++) loadStage(s, s);

    #pragma unroll 4
    for (int kt = 0; kt < NKITER; kt++) {
        const int buf = kt & (STAGES - 1);
        asm volatile("cp.async.wait_group %0;\n" :: "n"(STAGES - 2));
        __syncthreads();
        computeKs(buf, 0);
        const int nxt = kt + STAGES - 1;
        if (nxt < NKITER) loadStage(nxt & (STAGES - 1), nxt);
        else              asm volatile("cp.async.commit_group;\n");   // keep group count uniform
        computeKs(buf, 1);
    }

    // ---------------- epilogue: bias + RoPE + permuted store ----------------
    const int cg0 = n0g + hd * 128;      // global col of this warp's head base
    size_t headBase0; bool isQ, isK;
    isQ = (cg0 < NQ);
    isK = (cg0 >= NQ) && (cg0 < NQ + NKV);
    const bool doRope = (cg0 < NQ + NKV);
    const float* bias = g_bias + cg0;

    #pragma unroll
    for (int i = 0; i < 2; i++) {
        #pragma unroll
        for (int rr = 0; rr < 2; rr++) {
            const int r = wm * 32 + i * 16 + (lane >> 2) + rr * 8;
            const int m = m0 + r;
            const int bb = m >> 12;      // batch
            const int s  = m & 4095;     // seq pos
            size_t rowBase;
            if (isQ)      { int h = cg0 >> 7;              rowBase = ((size_t)(bb * 28 + h) * SEQ + s) * 128; }
            else if (isK) { int h = (cg0 - NQ) >> 7;       rowBase = QSZ + ((size_t)(bb * 4 + h) * SEQ + s) * 128; }
            else          { int h = (cg0 - NQ - NKV) >> 7; rowBase = QSZ + KSZ + ((size_t)(bb * 4 + h) * SEQ + s) * 128; }
            const float* cs = cosb + (size_t)m * 128;
            const float* sn = sinb + (size_t)m * 128;
            #pragma unroll
            for (int jn = 0; jn < 4; jn++) {
                const int dlo = half * 32 + jn * 8 + ((lane & 3) << 1);
                const int dhi = dlo + 64;
                float2 bl = *(const float2*)(bias + dlo);
                float2 bh = *(const float2*)(bias + dhi);
                float vl0 = acc[i][jn][rr * 2 + 0] + bl.x;
                float vl1 = acc[i][jn][rr * 2 + 1] + bl.y;
                float vh0 = acc[i][jn + 4][rr * 2 + 0] + bh.x;
                float vh1 = acc[i][jn + 4][rr * 2 + 1] + bh.y;
                float2 olo, ohi;
                if (doRope) {
                    float2 cl = *(const float2*)(cs + dlo);
                    float2 sl = *(const float2*)(sn + dlo);
                    float2 ch = *(const float2*)(cs + dhi);
                    float2 sh = *(const float2*)(sn + dhi);
                    olo.x = vl0 * cl.x - vh0 * sl.x;    // d < 64: q*cos - q[d+64]*sin
                    olo.y = vl1 * cl.y - vh1 * sl.y;
                    ohi.x = vh0 * ch.x + vl0 * sh.x;    // d >= 64: q*cos + q[d-64]*sin
                    ohi.y = vh1 * ch.y + vl1 * sh.y;
                } else {
                    olo = make_float2(vl0, vl1);
                    ohi = make_float2(vh0, vh1);
                }
                *(float2*)(out + rowBase + dlo) = olo;
                *(float2*)(out + rowBase + dhi) = ohi;
            }
        }
    }
}

// ---------------- launch ----------------

extern "C" void kernel_launch(void* const* d_in, const int* in_sizes, int n_in,
                              void* d_out, int out_size) {
    const float* hs   = (const float*)d_in[0];
    const float* cosb = (const float*)d_in[1];
    const float* sinb = (const float*)d_in[2];
    const float* Wq   = (const float*)d_in[3];
    const float* bq   = (const float*)d_in[4];
    const float* Wk   = (const float*)d_in[5];
    const float* bk   = (const float*)d_in[6];
    const float* Wv   = (const float*)d_in[7];
    const float* bv   = (const float*)d_in[8];
    float* out = (float*)d_out;

    // fp32 -> fp16 conversion passes (every call; no caching)
    conv_hidden<<<14336, 256>>>(hs);                 // 29360128 / 8 / 256
    conv_w<<<16128, 256>>>(Wq, Wk, Wv);              // 16515072 / 4 / 256
    conv_bias<<<18, 256>>>(bq, bk, bv);

    cudaFuncSetAttribute(qkv_gemm_rope, cudaFuncAttributeMaxDynamicSharedMemorySize, DYN_SMEM);
    dim3 grid(N_ALL / BN, M_TOT / BM);               // 18 x 64 (ht fastest)
    qkv_gemm_rope<<<grid, NTHREADS, DYN_SMEM>>>(cosb, sinb, out);
}